// round 16
// baseline (speedup 1.0000x reference)
#include <cuda_runtime.h>
#include <cuda_bf16.h>
#include <math.h>
#include <stdint.h>

#define DIMX 2048
#define KVDIM 512
#define QKV_N 3072
#define HD 64
#define NH 32
#define BATCH 2
#define SEQ 2048
#define M_ROWS (BATCH*SEQ)
#define QPAD 68     // float2 stride for Q/K interleaved hi/lo smem (flash)
#define VPAD 72     // float stride for V smem (flash)
#define ALD2 16     // uint32 row stride for swizzled bf16 smem tiles (GEMM)

// ---- scratch (module-static device memory) ----
__device__ __align__(16) __nv_bfloat16 g_w  [QKV_N*DIMX];       // ternarized [wq;wk;wv]
__device__ __align__(16) __nv_bfloat16 g_to [DIMX*DIMX];        // ternarized wo
__device__ __align__(16) __nv_bfloat16 g_xs [(size_t)3*M_ROWS*DIMX];  // x 3-split planes
__device__ __align__(16) __nv_bfloat16 g_aos[(size_t)2*M_ROWS*DIMX];  // ao 2-split planes
__device__ __align__(16) float g_qi [(size_t)2*M_ROWS*QKV_N];   // interleaved (hi,lo)
__device__ __align__(16) float g_vhi[(size_t)M_ROWS*KVDIM];     // compact V hi plane
__device__ float g_ao [(size_t)M_ROWS*DIMX];
__device__ float g_partial[4][256];
__device__ float g_thresh[4];

__device__ __forceinline__ uint32_t f2tf(float f) {
    uint32_t u; asm("cvt.rna.tf32.f32 %0, %1;" : "=r"(u) : "f"(f)); return u;
}
__device__ __forceinline__ float f2tff(float f) { return __uint_as_float(f2tf(f)); }
__device__ __forceinline__ uint32_t fu(float f) { return __float_as_uint(f); }
__device__ __forceinline__ void split2(float v, float& hi, float& lo) {
    hi = f2tff(v);
    lo = f2tff(v - hi);
}
__device__ __forceinline__ float bfr(float v) {
    return __bfloat162float(__float2bfloat16(v));
}
__device__ __forceinline__ uint32_t packbf(float a, float b) {
    __nv_bfloat162 p = __floats2bfloat162_rn(a, b);
    return *reinterpret_cast<uint32_t*>(&p);
}
__device__ __forceinline__ uint32_t smem_u32(const void* p) {
    uint32_t a;
    asm("{ .reg .u64 t; cvta.to.shared.u64 t, %1; cvt.u32.u64 %0, t; }" : "=r"(a) : "l"(p));
    return a;
}
#define CP16(dst, src) \
    asm volatile("cp.async.cg.shared.global [%0], [%1], 16;" :: "r"(dst), "l"(src))
#define CP_COMMIT()  asm volatile("cp.async.commit_group;" ::: "memory")
#define CP_WAIT1()   asm volatile("cp.async.wait_group 1;" ::: "memory")

#define LDSM_X4(r0, r1, r2, r3, addr) \
    asm volatile("ldmatrix.sync.aligned.m8n8.x4.shared.b16 {%0,%1,%2,%3}, [%4];" \
        : "=r"(r0), "=r"(r1), "=r"(r2), "=r"(r3) : "r"(addr))

// ---- fused |w| mean, pass 1 (grid.y = slot) ----
__global__ void abs_all_kernel(const float4* __restrict__ wq, const float4* __restrict__ wk,
                               const float4* __restrict__ wv, const float4* __restrict__ wo) {
    __shared__ float sd[256];
    int slot = blockIdx.y;
    const float4* w = slot == 0 ? wq : slot == 1 ? wk : slot == 2 ? wv : wo;
    int n4 = (slot == 0 || slot == 3) ? DIMX*DIMX/4 : KVDIM*DIMX/4;
    float s = 0.f;
    int stride = gridDim.x * blockDim.x;
    for (int i = blockIdx.x*blockDim.x + threadIdx.x; i < n4; i += stride) {
        float4 v = w[i];
        s += fabsf(v.x) + fabsf(v.y) + fabsf(v.z) + fabsf(v.w);
    }
    sd[threadIdx.x] = s;
    __syncthreads();
    for (int st = 128; st; st >>= 1) {
        if (threadIdx.x < st) sd[threadIdx.x] += sd[threadIdx.x + st];
        __syncthreads();
    }
    if (threadIdx.x == 0) g_partial[slot][blockIdx.x] = sd[0];
}

__global__ void finalize_kernel() {
    int slot = blockIdx.x;
    __shared__ float sd[256];
    sd[threadIdx.x] = g_partial[slot][threadIdx.x];
    __syncthreads();
    for (int st = 128; st; st >>= 1) {
        if (threadIdx.x < st) sd[threadIdx.x] += sd[threadIdx.x + st];
        __syncthreads();
    }
    if (threadIdx.x == 0) {
        const int ncounts[4] = {DIMX*DIMX, KVDIM*DIMX, KVDIM*DIMX, DIMX*DIMX};
        float scale = sd[0] / (float)ncounts[slot];
        g_thresh[slot] = 0.05f * fmaxf(scale, 1e-6f);
    }
}

// ---- fused ternarize->bf16 (slots 0-3) + x 3-split (slot 4), grid.y = slot ----
__global__ void tern_split_kernel(
    const float4* __restrict__ wq, const float4* __restrict__ wk,
    const float4* __restrict__ wv, const float4* __restrict__ wo,
    const float4* __restrict__ x,
    uint2* __restrict__ w3, uint2* __restrict__ to, uint2* __restrict__ xs)
{
    int slot = blockIdx.y;
    int i = blockIdx.x*256 + threadIdx.x;
    if (slot == 4) {
        const int n4 = M_ROWS*DIMX/4;
        if (i >= n4) return;
        float4 v = x[i];
        float h0 = bfr(v.x), h1 = bfr(v.y), h2 = bfr(v.z), h3 = bfr(v.w);
        xs[i] = make_uint2(packbf(h0, h1), packbf(h2, h3));
        float r0 = v.x - h0, r1 = v.y - h1, r2 = v.z - h2, r3 = v.w - h3;
        float m0 = bfr(r0), m1 = bfr(r1), m2 = bfr(r2), m3 = bfr(r3);
        xs[i + (size_t)n4] = make_uint2(packbf(m0, m1), packbf(m2, m3));
        xs[i + (size_t)2*n4] =
            make_uint2(packbf(r0 - m0, r1 - m1), packbf(r2 - m2, r3 - m3));
        return;
    }
    int n4 = (slot == 0 || slot == 3) ? DIMX*DIMX/4 : KVDIM*DIMX/4;
    if (i >= n4) return;
    const float4* w = slot == 0 ? wq : slot == 1 ? wk : slot == 2 ? wv : wo;
    uint2* dst = slot == 0 ? w3
               : slot == 1 ? (w3 + DIMX*DIMX/4)
               : slot == 2 ? (w3 + DIMX*DIMX/4 + KVDIM*DIMX/4)
               : to;
    float th = g_thresh[slot];
    float4 v = w[i];
    float o0 = v.x > th ? 1.f : (v.x < -th ? -1.f : 0.f);
    float o1 = v.y > th ? 1.f : (v.y < -th ? -1.f : 0.f);
    float o2 = v.z > th ? 1.f : (v.z < -th ? -1.f : 0.f);
    float o3 = v.w > th ? 1.f : (v.w < -th ? -1.f : 0.f);
    dst[i] = make_uint2(packbf(o0, o1), packbf(o2, o3));
}

// ---- split fp32 -> 2 bf16 planes (ao) ----
__global__ void split_bf2_kernel(const float4* __restrict__ src, uint2* __restrict__ dst, int n4) {
    int i = blockIdx.x*256 + threadIdx.x;
    if (i >= n4) return;
    float4 v = src[i];
    float h0 = bfr(v.x), h1 = bfr(v.y), h2 = bfr(v.z), h3 = bfr(v.w);
    dst[i] = make_uint2(packbf(h0, h1), packbf(h2, h3));
    dst[i + (size_t)n4] =
        make_uint2(packbf(v.x - h0, v.y - h1), packbf(v.z - h2, v.w - h3));
}

#define MMA_BF16(d, a, b0v, b1v)                                             \
    asm volatile("mma.sync.aligned.m16n8k16.row.col.f32.bf16.bf16.f32 "      \
        "{%0,%1,%2,%3}, {%4,%5,%6,%7}, {%8,%9}, {%0,%1,%2,%3};"              \
        : "+f"(d[0]), "+f"(d[1]), "+f"(d[2]), "+f"(d[3])                     \
        : "r"(a[0]), "r"(a[1]), "r"(a[2]), "r"(a[3]), "r"(b0v), "r"(b1v))

#define MMA_TF32(d, a, b0v, b1v)                                             \
    asm volatile("mma.sync.aligned.m16n8k8.row.col.f32.tf32.tf32.f32 "       \
        "{%0,%1,%2,%3}, {%4,%5,%6,%7}, {%8,%9}, {%0,%1,%2,%3};"              \
        : "+f"(d[0]), "+f"(d[1]), "+f"(d[2]), "+f"(d[3])                     \
        : "r"(a[0]), "r"(a[1]), "r"(a[2]), "r"(a[3]), "r"(b0v), "r"(b1v))

// ---- C[M,N] = A*B^T, bf16, 2-stage ring, 3 CTAs/SM, per-sp a-frag reuse ----
template<int NSPLIT, bool SPLIT_OUT>
__global__ __launch_bounds__(256, 3) void gemm_async(
    const __nv_bfloat16* __restrict__ Abf, const __nv_bfloat16* __restrict__ B,
    float* __restrict__ C, float* __restrict__ Caux, int Mtot, int N, int K)
{
    extern __shared__ __align__(16) uint32_t smu[];
    const int STG_U32 = (NSPLIT+1)*128*ALD2;
    int tid = threadIdx.x;
    int wid = tid >> 5, lane = tid & 31;
    int g = lane >> 2, t = lane & 3;
    int wm = (wid & 1) * 64, wn = (wid >> 1) * 32;
    int lr = tid >> 1, half = tid & 1;

    // ldmatrix lane decomposition
    int lrow8 = lane & 7;
    int lsel  = lane >> 3;
    int a_row_add = (lsel & 1) << 3;
    int b_row_add = (lsel >> 1) << 3;
    int cselA = lsel >> 1;
    int cselB = lsel & 1;
    int swzA = ((lrow8 + a_row_add) >> 1) & 3;
    int swzB = ((lrow8 + b_row_add) >> 1) & 3;
    int swzS = (lr >> 1) & 3;

    uint32_t sb = smem_u32(smu);
    uint32_t stBase[2] = { sb, sb + (uint32_t)STG_U32*4 };

    int brow = blockIdx.y*128 + lr;
    const __nv_bfloat16* Brow = B + (size_t)(blockIdx.x*128 + lr)*K;

    float acc[4][4][4];
    #pragma unroll
    for (int mt = 0; mt < 4; mt++)
        #pragma unroll
        for (int nt = 0; nt < 4; nt++)
            #pragma unroll
            for (int r = 0; r < 4; r++) acc[mt][nt][r] = 0.f;

    uint32_t cs0 = (uint32_t)((half*2)     ^ swzS) * 16;
    uint32_t cs1 = (uint32_t)((half*2 + 1) ^ swzS) * 16;

    auto issue = [&](int c, uint32_t base) {
        int k0 = c*32;
        #pragma unroll
        for (int sp = 0; sp < NSPLIT; sp++) {
            const __nv_bfloat16* src = Abf + ((size_t)sp*Mtot + brow)*K + k0 + half*16;
            uint32_t rowb = base + (uint32_t)((sp*128 + lr)*ALD2)*4;
            CP16(rowb + cs0, src);
            CP16(rowb + cs1, src + 8);
        }
        const __nv_bfloat16* bs = Brow + k0 + half*16;
        uint32_t rowb = base + (uint32_t)((NSPLIT*128 + lr)*ALD2)*4;
        CP16(rowb + cs0, bs);
        CP16(rowb + cs1, bs + 8);
        CP_COMMIT();
    };

    int nch = K/32;
    issue(0, stBase[0]);
    issue(1, stBase[1]);

    int sidx = 0;
    for (int c = 0; c < nch; c++) {
        CP_WAIT1();
        __syncthreads();
        uint32_t stAddr = stBase[sidx];
        #pragma unroll
        for (int s = 0; s < 2; s++) {
            uint32_t b[4][2];
            uint32_t chA = (uint32_t)(((s*2 + cselA) ^ swzA) * 4);
            uint32_t chB = (uint32_t)(((s*2 + cselB) ^ swzB) * 4);
            #pragma unroll
            for (int ntp = 0; ntp < 2; ntp++) {
                uint32_t addr = stAddr + 4u*(
                    (uint32_t)(NSPLIT*128 + wn + ntp*16 + b_row_add + lrow8)*ALD2 + chB);
                uint32_t r0, r1, r2, r3;
                LDSM_X4(r0, r1, r2, r3, addr);
                b[ntp*2][0]   = r0; b[ntp*2][1]   = r1;
                b[ntp*2+1][0] = r2; b[ntp*2+1][1] = r3;
            }
            // per-sp fragment reuse: a[4][4] live only within one sp block
            #pragma unroll
            for (int sp = 0; sp < NSPLIT; sp++) {
                uint32_t a[4][4];
                #pragma unroll
                for (int mt = 0; mt < 4; mt++) {
                    uint32_t addr = stAddr + 4u*(
                        (uint32_t)(sp*128 + wm + mt*16 + lrow8 + a_row_add)*ALD2 + chA);
                    LDSM_X4(a[mt][0], a[mt][1], a[mt][2], a[mt][3], addr);
                }
                #pragma unroll
                for (int mt = 0; mt < 4; mt++)
                    #pragma unroll
                    for (int nt = 0; nt < 4; nt++)
                        MMA_BF16(acc[mt][nt], a[mt], b[nt][0], b[nt][1]);
            }
        }
        __syncthreads();
        if (c + 2 < nch) issue(c + 2, stAddr);
        else CP_COMMIT();
        sidx ^= 1;
    }

    #pragma unroll
    for (int mt = 0; mt < 4; mt++) {
        int r0 = blockIdx.y*128 + wm + mt*16 + g;
        #pragma unroll
        for (int nt = 0; nt < 4; nt++) {
            int col = blockIdx.x*128 + wn + nt*8 + t*2;
            if (SPLIT_OUT) {
                float h0,l0,h1,l1,h2,l2,h3,l3;
                split2(acc[mt][nt][0], h0, l0); split2(acc[mt][nt][1], h1, l1);
                split2(acc[mt][nt][2], h2, l2); split2(acc[mt][nt][3], h3, l3);
                float2* Ci = reinterpret_cast<float2*>(C);
                *reinterpret_cast<float4*>(&Ci[(size_t)r0*N + col]) =
                    make_float4(h0, l0, h1, l1);
                *reinterpret_cast<float4*>(&Ci[(size_t)(r0+8)*N + col]) =
                    make_float4(h2, l2, h3, l3);
                if (col >= DIMX + KVDIM) {
                    int vc = col - (DIMX + KVDIM);
                    *reinterpret_cast<float2*>(&Caux[(size_t)r0*KVDIM + vc]) =
                        make_float2(h0, h1);
                    *reinterpret_cast<float2*>(&Caux[(size_t)(r0+8)*KVDIM + vc]) =
                        make_float2(h2, h3);
                }
            } else {
                *reinterpret_cast<float2*>(C + (size_t)r0*N + col) =
                    make_float2(acc[mt][nt][0], acc[mt][nt][1]);
                *reinterpret_cast<float2*>(C + (size_t)(r0+8)*N + col) =
                    make_float2(acc[mt][nt][2], acc[mt][nt][3]);
            }
        }
    }
}

// ---- GQA-merged causal flash attention (body frozen) ----
__global__ __launch_bounds__(256) void flash_kernel(
    const float2* __restrict__ Qi, const float* __restrict__ Vhi,
    float* __restrict__ O)
{
    extern __shared__ float smf[];
    float2* Qs = reinterpret_cast<float2*>(smf);
    float2* Ks = reinterpret_cast<float2*>(smf + 256*QPAD*2);
    float*  Vs = smf + 256*QPAD*2 + 64*QPAD*2;

    int gcomb = blockIdx.x;
    int gkv = gcomb >> 1;
    int b   = gcomb & 1;
    int qb  = 31 - blockIdx.y;

    int tid = threadIdx.x;
    int wid = tid >> 5, lane = tid & 31;
    int g = lane >> 2, t = lane & 3;
    int hh = wid >> 1;
    int h  = gkv*4 + hh;
    int wr = (wid & 1) * 32;

    {
        size_t rowbase = (size_t)(b*SEQ + qb*64);
        #pragma unroll
        for (int it = 0; it < 32; it++) {
            int pidx = tid + it*256;
            int qrow = pidx >> 5;
            int c2 = pidx & 31;
            int head = gkv*4 + (qrow >> 6);
            size_t goff = (rowbase + (qrow & 63))*QKV_N + head*HD + c2*2;
            *reinterpret_cast<float4*>(&Qs[qrow*QPAD + c2*2]) =
                *reinterpret_cast<const float4*>(&Qi[goff]);
        }
    }

    float m_i[4], l_i[4];
    float o_acc[2][8][4];
    #pragma unroll
    for (int i = 0; i < 4; i++) { m_i[i] = -INFINITY; l_i[i] = 0.f; }
    #pragma unroll
    for (int mt = 0; mt < 2; mt++)
        #pragma unroll
        for (int dt = 0; dt < 8; dt++)
            #pragma unroll
            for (int r = 0; r < 4; r++) o_acc[mt][dt][r] = 0.f;

    for (int kb = 0; kb <= qb; kb++) {
        __syncthreads();
        {
            size_t krowbase = (size_t)(b*SEQ + kb*64);
            #pragma unroll
            for (int it = 0; it < 8; it++) {
                int pidx = tid + it*256;
                int kr = pidx >> 5, c2 = pidx & 31;
                size_t goff = (krowbase + kr)*QKV_N + DIMX + gkv*HD + c2*2;
                *reinterpret_cast<float4*>(&Ks[kr*QPAD + c2*2]) =
                    *reinterpret_cast<const float4*>(&Qi[goff]);
            }
            #pragma unroll
            for (int it = 0; it < 4; it++) {
                int fidx = tid + it*256;
                int vr = fidx >> 4, d4 = fidx & 15;
                size_t goff = (krowbase + vr)*KVDIM + gkv*HD + d4*4;
                *reinterpret_cast<float4*>(&Vs[vr*VPAD + d4*4]) =
                    *reinterpret_cast<const float4*>(Vhi + goff);
            }
        }
        __syncthreads();

        float s[2][8][4];
        #pragma unroll
        for (int mt = 0; mt < 2; mt++)
            #pragma unroll
            for (int nt = 0; nt < 8; nt++)
                #pragma unroll
                for (int r = 0; r < 4; r++) s[mt][nt][r] = 0.f;

        #pragma unroll
        for (int ks = 0; ks < 8; ks++) {
            int kk = ks*8;
            uint32_t ah[2][4], al[2][4];
            #pragma unroll
            for (int mt = 0; mt < 2; mt++) {
                int row = hh*64 + wr + mt*16 + g;
                float2 q00 = Qs[row*QPAD + kk + t];
                float2 q01 = Qs[row*QPAD + kk + t + 4];
                float2 q10 = Qs[(row+8)*QPAD + kk + t];
                float2 q11 = Qs[(row+8)*QPAD + kk + t + 4];
                ah[mt][0] = fu(q00.x); al[mt][0] = fu(q00.y);
                ah[mt][1] = fu(q10.x); al[mt][1] = fu(q10.y);
                ah[mt][2] = fu(q01.x); al[mt][2] = fu(q01.y);
                ah[mt][3] = fu(q11.x); al[mt][3] = fu(q11.y);
            }
            #pragma unroll
            for (int nt = 0; nt < 8; nt++) {
                float2 k0 = Ks[(nt*8+g)*QPAD + kk + t];
                float2 k1 = Ks[(nt*8+g)*QPAD + kk + t + 4];
                uint32_t bh0 = fu(k0.x), bl0 = fu(k0.y);
                uint32_t bh1 = fu(k1.x), bl1 = fu(k1.y);
                MMA_TF32(s[0][nt], ah[0], bh0, bh1);
                MMA_TF32(s[1][nt], ah[1], bh0, bh1);
                MMA_TF32(s[0][nt], ah[0], bl0, bl1);
                MMA_TF32(s[1][nt], ah[1], bl0, bl1);
                MMA_TF32(s[0][nt], al[0], bh0, bh1);
                MMA_TF32(s[1][nt], al[1], bh0, bh1);
            }
        }

        const float smul = 0.125f;
        if (kb == qb) {
            #pragma unroll
            for (int mt = 0; mt < 2; mt++) {
                int qr = wr + mt*16 + g;
                #pragma unroll
                for (int nt = 0; nt < 8; nt++) {
                    int c0 = nt*8 + t*2;
                    s[mt][nt][0] = (c0     <= qr)     ? s[mt][nt][0]*smul : -INFINITY;
                    s[mt][nt][1] = (c0 + 1 <= qr)     ? s[mt][nt][1]*smul : -INFINITY;
                    s[mt][nt][2] = (c0     <= qr + 8) ? s[mt][nt][2]*smul : -INFINITY;
                    s[mt][nt][3] = (c0 + 1 <= qr + 8) ? s[mt][nt][3]*smul : -INFINITY;
                }
            }
        } else {
            #pragma unroll
            for (int mt = 0; mt < 2; mt++)
                #pragma unroll
                for (int nt = 0; nt < 8; nt++)
                    #pragma unroll
                    for (int r = 0; r < 4; r++) s[mt][nt][r] *= smul;
        }

        #pragma unroll
        for (int mt = 0; mt < 2; mt++)
            #pragma unroll
            for (int rr = 0; rr < 2; rr++) {
                int si = mt*2 + rr;
                float mx = -INFINITY;
                #pragma unroll
                for (int nt = 0; nt < 8; nt++)
                    mx = fmaxf(mx, fmaxf(s[mt][nt][2*rr], s[mt][nt][2*rr+1]));
                mx = fmaxf(mx, __shfl_xor_sync(0xffffffffu, mx, 1));
                mx = fmaxf(mx, __shfl_xor_sync(0xffffffffu, mx, 2));
                float m_new = fmaxf(m_i[si], mx);
                float alpha = __expf(m_i[si] - m_new);
                float rs = 0.f;
                #pragma unroll
                for (int nt = 0; nt < 8; nt++) {
                    float p0 = __expf(s[mt][nt][2*rr]   - m_new);
                    float p1 = __expf(s[mt][nt][2*rr+1] - m_new);
                    s[mt][nt][2*rr] = p0; s[mt][nt][2*rr+1] = p1;
                    rs += p0 + p1;
                }
                rs += __shfl_xor_sync(0xffffffffu, rs, 1);
                rs += __shfl_xor_sync(0xffffffffu, rs, 2);
                l_i[si] = l_i[si]*alpha + rs;
                m_i[si] = m_new;
                #pragma unroll
                for (int dt = 0; dt < 8; dt++) {
                    o_acc[mt][dt][2*rr]   *= alpha;
                    o_acc[mt][dt][2*rr+1] *= alpha;
                }
            }

        #pragma unroll
        for (int ks = 0; ks < 8; ks++) {
            int kk = ks*8;
            uint32_t pa[2][4];
            int srcA = (lane & 28) | (t >> 1);
            int srcB = srcA + 2;
            #pragma unroll
            for (int mt = 0; mt < 2; mt++) {
                float x0 = __shfl_sync(0xffffffffu, s[mt][ks][0], srcA);
                float x1 = __shfl_sync(0xffffffffu, s[mt][ks][1], srcA);
                float y0 = __shfl_sync(0xffffffffu, s[mt][ks][0], srcB);
                float y1 = __shfl_sync(0xffffffffu, s[mt][ks][1], srcB);
                float x2 = __shfl_sync(0xffffffffu, s[mt][ks][2], srcA);
                float x3 = __shfl_sync(0xffffffffu, s[mt][ks][3], srcA);
                float y2 = __shfl_sync(0xffffffffu, s[mt][ks][2], srcB);
                float y3 = __shfl_sync(0xffffffffu, s[mt][ks][3], srcB);
                float a0 = (t & 1) ? x1 : x0;
                float a1 = (t & 1) ? x3 : x2;
                float a2 = (t & 1) ? y1 : y0;
                float a3 = (t & 1) ? y3 : y2;
                pa[mt][0] = f2tf(a0); pa[mt][1] = f2tf(a1);
                pa[mt][2] = f2tf(a2); pa[mt][3] = f2tf(a3);
            }
            #pragma unroll
            for (int dt = 0; dt < 8; dt++) {
                uint32_t v0 = fu(Vs[(kk+t)*VPAD + dt*8 + g]);
                uint32_t v1 = fu(Vs[(kk+t+4)*VPAD + dt*8 + g]);
                MMA_TF32(o_acc[0][dt], pa[0], v0, v1);
                MMA_TF32(o_acc[1][dt], pa[1], v0, v1);
            }
        }
    }

    #pragma unroll
    for (int mt = 0; mt < 2; mt++) {
        float inv0 = 1.f / l_i[mt*2];
        float inv1 = 1.f / l_i[mt*2+1];
        float* Og = O + (size_t)(b*SEQ + qb*64 + wr + mt*16 + g)*DIMX + h*HD;
        #pragma unroll
        for (int dt = 0; dt < 8; dt++) {
            *reinterpret_cast<float2*>(Og + dt*8 + t*2) =
                make_float2(o_acc[mt][dt][0]*inv0, o_acc[mt][dt][1]*inv0);
            *reinterpret_cast<float2*>(Og + (size_t)8*DIMX + dt*8 + t*2) =
                make_float2(o_acc[mt][dt][2]*inv1, o_acc[mt][dt][3]*inv1);
        }
    }
}

extern "C" void kernel_launch(void* const* d_in, const int* in_sizes, int n_in,
                              void* d_out, int out_size)
{
    const float* x  = (const float*)d_in[0];
    const float* wq = (const float*)d_in[1];
    const float* wk = (const float*)d_in[2];
    const float* wv = (const float*)d_in[3];
    const float* wo = (const float*)d_in[4];
    float* out = (float*)d_out;

    __nv_bfloat16 *w3, *to, *xs, *aos;
    float *qi, *vhi, *ao;
    cudaGetSymbolAddress((void**)&w3,  g_w);
    cudaGetSymbolAddress((void**)&to,  g_to);
    cudaGetSymbolAddress((void**)&xs,  g_xs);
    cudaGetSymbolAddress((void**)&aos, g_aos);
    cudaGetSymbolAddress((void**)&qi,  g_qi);
    cudaGetSymbolAddress((void**)&vhi, g_vhi);
    cudaGetSymbolAddress((void**)&ao,  g_ao);

    // 1) fused |w| mean + thresholds
    abs_all_kernel<<<dim3(256, 4), 256>>>((const float4*)wq, (const float4*)wk,
                                          (const float4*)wv, (const float4*)wo);
    finalize_kernel<<<4, 256>>>();

    // 2) fused ternarize + x 3-split
    tern_split_kernel<<<dim3(M_ROWS*DIMX/4/256, 5), 256>>>(
        (const float4*)wq, (const float4*)wk, (const float4*)wv, (const float4*)wo,
        (const float4*)x, (uint2*)w3, (uint2*)to, (uint2*)xs);

    // 3) QKV projection (2-stage, 3 CTAs/SM)   [launch #4 -> profiled]
    int gsm1 = 2 * 4*128*ALD2 * 4;
    cudaFuncSetAttribute(gemm_async<3,true>,
                         cudaFuncAttributeMaxDynamicSharedMemorySize, gsm1);
    gemm_async<3,true><<<dim3(QKV_N/128, M_ROWS/128), 256, gsm1>>>(
        xs, w3, qi, vhi, M_ROWS, QKV_N, DIMX);

    // 4) attention (GQA-merged)
    int fsm = (256*QPAD*2 + 64*QPAD*2 + 64*VPAD) * 4;
    cudaFuncSetAttribute(flash_kernel,
                         cudaFuncAttributeMaxDynamicSharedMemorySize, fsm);
    flash_kernel<<<dim3(16, 32), 256, fsm>>>((const float2*)qi, vhi, ao);

    // 5) pre-split ao into 2 bf16 planes
    split_bf2_kernel<<<(M_ROWS*DIMX/4)/256, 256>>>(
        (const float4*)ao, (uint2*)aos, M_ROWS*DIMX/4);

    // 6) output projection (2-stage, 3 CTAs/SM)
    int gsm2 = 2 * 3*128*ALD2 * 4;
    cudaFuncSetAttribute(gemm_async<2,false>,
                         cudaFuncAttributeMaxDynamicSharedMemorySize, gsm2);
    gemm_async<2,false><<<dim3(DIMX/128, M_ROWS/128), 256, gsm2>>>(
        aos, to, out, nullptr, M_ROWS, DIMX, DIMX);
}

// round 17
// speedup vs baseline: 1.2541x; 1.2541x over previous
#include <cuda_runtime.h>
#include <cuda_bf16.h>
#include <math.h>
#include <stdint.h>

#define DIMX 2048
#define KVDIM 512
#define QKV_N 3072
#define HD 64
#define NH 32
#define BATCH 2
#define SEQ 2048
#define M_ROWS (BATCH*SEQ)
#define QPAD 68     // float2 stride for Q/K interleaved hi/lo smem (flash)
#define VPAD 72     // float stride for V smem (flash)
#define ALD2 16     // uint32 row stride for swizzled bf16 smem tiles (GEMM)

// ---- scratch (module-static device memory) ----
__device__ __align__(16) __nv_bfloat16 g_w  [QKV_N*DIMX];
__device__ __align__(16) __nv_bfloat16 g_to [DIMX*DIMX];
__device__ __align__(16) __nv_bfloat16 g_xs [(size_t)3*M_ROWS*DIMX];
__device__ __align__(16) __nv_bfloat16 g_aos[(size_t)2*M_ROWS*DIMX];
__device__ __align__(16) float g_qi [(size_t)2*M_ROWS*QKV_N];
__device__ __align__(16) float g_vhi[(size_t)M_ROWS*KVDIM];
__device__ float g_ao [(size_t)M_ROWS*DIMX];
__device__ float g_partial[4][256];
__device__ float g_thresh[4];

__device__ __forceinline__ uint32_t f2tf(float f) {
    uint32_t u; asm("cvt.rna.tf32.f32 %0, %1;" : "=r"(u) : "f"(f)); return u;
}
__device__ __forceinline__ float f2tff(float f) { return __uint_as_float(f2tf(f)); }
__device__ __forceinline__ uint32_t fu(float f) { return __float_as_uint(f); }
__device__ __forceinline__ void split2(float v, float& hi, float& lo) {
    hi = f2tff(v);
    lo = f2tff(v - hi);
}
__device__ __forceinline__ float bfr(float v) {
    return __bfloat162float(__float2bfloat16(v));
}
__device__ __forceinline__ uint32_t packbf(float a, float b) {
    __nv_bfloat162 p = __floats2bfloat162_rn(a, b);
    return *reinterpret_cast<uint32_t*>(&p);
}
__device__ __forceinline__ uint32_t smem_u32(const void* p) {
    uint32_t a;
    asm("{ .reg .u64 t; cvta.to.shared.u64 t, %1; cvt.u32.u64 %0, t; }" : "=r"(a) : "l"(p));
    return a;
}
#define CP16(dst, src) \
    asm volatile("cp.async.cg.shared.global [%0], [%1], 16;" :: "r"(dst), "l"(src))
#define CP_COMMIT()  asm volatile("cp.async.commit_group;" ::: "memory")
#define CP_WAIT2()   asm volatile("cp.async.wait_group 2;" ::: "memory")

#define LDSM_X4(r0, r1, r2, r3, addr) \
    asm volatile("ldmatrix.sync.aligned.m8n8.x4.shared.b16 {%0,%1,%2,%3}, [%4];" \
        : "=r"(r0), "=r"(r1), "=r"(r2), "=r"(r3) : "r"(addr))

// ---- fused |w| mean, pass 1 (grid.y = slot) ----
__global__ void abs_all_kernel(const float4* __restrict__ wq, const float4* __restrict__ wk,
                               const float4* __restrict__ wv, const float4* __restrict__ wo) {
    __shared__ float sd[256];
    int slot = blockIdx.y;
    const float4* w = slot == 0 ? wq : slot == 1 ? wk : slot == 2 ? wv : wo;
    int n4 = (slot == 0 || slot == 3) ? DIMX*DIMX/4 : KVDIM*DIMX/4;
    float s = 0.f;
    int stride = gridDim.x * blockDim.x;
    for (int i = blockIdx.x*blockDim.x + threadIdx.x; i < n4; i += stride) {
        float4 v = w[i];
        s += fabsf(v.x) + fabsf(v.y) + fabsf(v.z) + fabsf(v.w);
    }
    sd[threadIdx.x] = s;
    __syncthreads();
    for (int st = 128; st; st >>= 1) {
        if (threadIdx.x < st) sd[threadIdx.x] += sd[threadIdx.x + st];
        __syncthreads();
    }
    if (threadIdx.x == 0) g_partial[slot][blockIdx.x] = sd[0];
}

__global__ void finalize_kernel() {
    int slot = blockIdx.x;
    __shared__ float sd[256];
    sd[threadIdx.x] = g_partial[slot][threadIdx.x];
    __syncthreads();
    for (int st = 128; st; st >>= 1) {
        if (threadIdx.x < st) sd[threadIdx.x] += sd[threadIdx.x + st];
        __syncthreads();
    }
    if (threadIdx.x == 0) {
        const int ncounts[4] = {DIMX*DIMX, KVDIM*DIMX, KVDIM*DIMX, DIMX*DIMX};
        float scale = sd[0] / (float)ncounts[slot];
        g_thresh[slot] = 0.05f * fmaxf(scale, 1e-6f);
    }
}

// ---- fused ternarize->bf16 (slots 0-3) + x 3-split (slot 4) ----
__global__ void tern_split_kernel(
    const float4* __restrict__ wq, const float4* __restrict__ wk,
    const float4* __restrict__ wv, const float4* __restrict__ wo,
    const float4* __restrict__ x,
    uint2* __restrict__ w3, uint2* __restrict__ to, uint2* __restrict__ xs)
{
    int slot = blockIdx.y;
    int i = blockIdx.x*256 + threadIdx.x;
    if (slot == 4) {
        const int n4 = M_ROWS*DIMX/4;
        if (i >= n4) return;
        float4 v = x[i];
        float h0 = bfr(v.x), h1 = bfr(v.y), h2 = bfr(v.z), h3 = bfr(v.w);
        xs[i] = make_uint2(packbf(h0, h1), packbf(h2, h3));
        float r0 = v.x - h0, r1 = v.y - h1, r2 = v.z - h2, r3 = v.w - h3;
        float m0 = bfr(r0), m1 = bfr(r1), m2 = bfr(r2), m3 = bfr(r3);
        xs[i + (size_t)n4] = make_uint2(packbf(m0, m1), packbf(m2, m3));
        xs[i + (size_t)2*n4] =
            make_uint2(packbf(r0 - m0, r1 - m1), packbf(r2 - m2, r3 - m3));
        return;
    }
    int n4 = (slot == 0 || slot == 3) ? DIMX*DIMX/4 : KVDIM*DIMX/4;
    if (i >= n4) return;
    const float4* w = slot == 0 ? wq : slot == 1 ? wk : slot == 2 ? wv : wo;
    uint2* dst = slot == 0 ? w3
               : slot == 1 ? (w3 + DIMX*DIMX/4)
               : slot == 2 ? (w3 + DIMX*DIMX/4 + KVDIM*DIMX/4)
               : to;
    float th = g_thresh[slot];
    float4 v = w[i];
    float o0 = v.x > th ? 1.f : (v.x < -th ? -1.f : 0.f);
    float o1 = v.y > th ? 1.f : (v.y < -th ? -1.f : 0.f);
    float o2 = v.z > th ? 1.f : (v.z < -th ? -1.f : 0.f);
    float o3 = v.w > th ? 1.f : (v.w < -th ? -1.f : 0.f);
    dst[i] = make_uint2(packbf(o0, o1), packbf(o2, o3));
}

// ---- split fp32 -> 2 bf16 planes (ao) ----
__global__ void split_bf2_kernel(const float4* __restrict__ src, uint2* __restrict__ dst, int n4) {
    int i = blockIdx.x*256 + threadIdx.x;
    if (i >= n4) return;
    float4 v = src[i];
    float h0 = bfr(v.x), h1 = bfr(v.y), h2 = bfr(v.z), h3 = bfr(v.w);
    dst[i] = make_uint2(packbf(h0, h1), packbf(h2, h3));
    dst[i + (size_t)n4] =
        make_uint2(packbf(v.x - h0, v.y - h1), packbf(v.z - h2, v.w - h3));
}

#define MMA_BF16(d, a, b0v, b1v)                                             \
    asm volatile("mma.sync.aligned.m16n8k16.row.col.f32.bf16.bf16.f32 "      \
        "{%0,%1,%2,%3}, {%4,%5,%6,%7}, {%8,%9}, {%0,%1,%2,%3};"              \
        : "+f"(d[0]), "+f"(d[1]), "+f"(d[2]), "+f"(d[3])                     \
        : "r"(a[0]), "r"(a[1]), "r"(a[2]), "r"(a[3]), "r"(b0v), "r"(b1v))

#define MMA_TF32(d, a, b0v, b1v)                                             \
    asm volatile("mma.sync.aligned.m16n8k8.row.col.f32.tf32.tf32.f32 "       \
        "{%0,%1,%2,%3}, {%4,%5,%6,%7}, {%8,%9}, {%0,%1,%2,%3};"              \
        : "+f"(d[0]), "+f"(d[1]), "+f"(d[2]), "+f"(d[3])                     \
        : "r"(a[0]), "r"(a[1]), "r"(a[2]), "r"(a[3]), "r"(b0v), "r"(b1v))

// ---- C[M,N] = A*B^T, bf16, 3-stage ring (R14 config restored) ----
template<int NSPLIT, bool SPLIT_OUT>
__global__ __launch_bounds__(256) void gemm_async(
    const __nv_bfloat16* __restrict__ Abf, const __nv_bfloat16* __restrict__ B,
    float* __restrict__ C, float* __restrict__ Caux, int Mtot, int N, int K)
{
    extern __shared__ __align__(16) uint32_t smu[];
    const int STG_U32 = (NSPLIT+1)*128*ALD2;
    int tid = threadIdx.x;
    int wid = tid >> 5, lane = tid & 31;
    int g = lane >> 2, t = lane & 3;
    int wm = (wid & 1) * 64, wn = (wid >> 1) * 32;
    int lr = tid >> 1, half = tid & 1;

    int lrow8 = lane & 7;
    int lsel  = lane >> 3;
    int a_row_add = (lsel & 1) << 3;
    int b_row_add = (lsel >> 1) << 3;
    int cselA = lsel >> 1;
    int cselB = lsel & 1;
    int swzA = ((lrow8 + a_row_add) >> 1) & 3;
    int swzB = ((lrow8 + b_row_add) >> 1) & 3;
    int swzS = (lr >> 1) & 3;

    uint32_t sb = smem_u32(smu);
    uint32_t stBase[3] = { sb, sb + (uint32_t)STG_U32*4, sb + (uint32_t)STG_U32*8 };

    int brow = blockIdx.y*128 + lr;
    const __nv_bfloat16* Brow = B + (size_t)(blockIdx.x*128 + lr)*K;

    float acc[4][4][4];
    #pragma unroll
    for (int mt = 0; mt < 4; mt++)
        #pragma unroll
        for (int nt = 0; nt < 4; nt++)
            #pragma unroll
            for (int r = 0; r < 4; r++) acc[mt][nt][r] = 0.f;

    uint32_t cs0 = (uint32_t)((half*2)     ^ swzS) * 16;
    uint32_t cs1 = (uint32_t)((half*2 + 1) ^ swzS) * 16;

    auto issue = [&](int c, uint32_t base) {
        int k0 = c*32;
        #pragma unroll
        for (int sp = 0; sp < NSPLIT; sp++) {
            const __nv_bfloat16* src = Abf + ((size_t)sp*Mtot + brow)*K + k0 + half*16;
            uint32_t rowb = base + (uint32_t)((sp*128 + lr)*ALD2)*4;
            CP16(rowb + cs0, src);
            CP16(rowb + cs1, src + 8);
        }
        const __nv_bfloat16* bs = Brow + k0 + half*16;
        uint32_t rowb = base + (uint32_t)((NSPLIT*128 + lr)*ALD2)*4;
        CP16(rowb + cs0, bs);
        CP16(rowb + cs1, bs + 8);
        CP_COMMIT();
    };

    int nch = K/32;
    issue(0, stBase[0]);
    issue(1, stBase[1]);
    issue(2, stBase[2]);

    int sidx = 0;
    for (int c = 0; c < nch; c++) {
        CP_WAIT2();
        __syncthreads();
        uint32_t stAddr = stBase[sidx];
        #pragma unroll
        for (int s = 0; s < 2; s++) {
            uint32_t a[NSPLIT][4][4], b[4][2];
            uint32_t chA = (uint32_t)(((s*2 + cselA) ^ swzA) * 4);
            uint32_t chB = (uint32_t)(((s*2 + cselB) ^ swzB) * 4);
            #pragma unroll
            for (int mt = 0; mt < 4; mt++) {
                #pragma unroll
                for (int sp = 0; sp < NSPLIT; sp++) {
                    uint32_t addr = stAddr + 4u*(
                        (uint32_t)(sp*128 + wm + mt*16 + lrow8 + a_row_add)*ALD2 + chA);
                    LDSM_X4(a[sp][mt][0], a[sp][mt][1], a[sp][mt][2], a[sp][mt][3], addr);
                }
            }
            #pragma unroll
            for (int ntp = 0; ntp < 2; ntp++) {
                uint32_t addr = stAddr + 4u*(
                    (uint32_t)(NSPLIT*128 + wn + ntp*16 + b_row_add + lrow8)*ALD2 + chB);
                uint32_t r0, r1, r2, r3;
                LDSM_X4(r0, r1, r2, r3, addr);
                b[ntp*2][0]   = r0; b[ntp*2][1]   = r1;
                b[ntp*2+1][0] = r2; b[ntp*2+1][1] = r3;
            }
            #pragma unroll
            for (int sp = 0; sp < NSPLIT; sp++)
                #pragma unroll
                for (int mt = 0; mt < 4; mt++)
                    #pragma unroll
                    for (int nt = 0; nt < 4; nt++)
                        MMA_BF16(acc[mt][nt], a[sp][mt], b[nt][0], b[nt][1]);
        }
        __syncthreads();
        if (c + 3 < nch) issue(c + 3, stAddr);
        else CP_COMMIT();
        if (++sidx == 3) sidx = 0;
    }

    #pragma unroll
    for (int mt = 0; mt < 4; mt++) {
        int r0 = blockIdx.y*128 + wm + mt*16 + g;
        #pragma unroll
        for (int nt = 0; nt < 4; nt++) {
            int col = blockIdx.x*128 + wn + nt*8 + t*2;
            if (SPLIT_OUT) {
                float h0,l0,h1,l1,h2,l2,h3,l3;
                split2(acc[mt][nt][0], h0, l0); split2(acc[mt][nt][1], h1, l1);
                split2(acc[mt][nt][2], h2, l2); split2(acc[mt][nt][3], h3, l3);
                float2* Ci = reinterpret_cast<float2*>(C);
                *reinterpret_cast<float4*>(&Ci[(size_t)r0*N + col]) =
                    make_float4(h0, l0, h1, l1);
                *reinterpret_cast<float4*>(&Ci[(size_t)(r0+8)*N + col]) =
                    make_float4(h2, l2, h3, l3);
                if (col >= DIMX + KVDIM) {
                    int vc = col - (DIMX + KVDIM);
                    *reinterpret_cast<float2*>(&Caux[(size_t)r0*KVDIM + vc]) =
                        make_float2(h0, h1);
                    *reinterpret_cast<float2*>(&Caux[(size_t)(r0+8)*KVDIM + vc]) =
                        make_float2(h2, h3);
                }
            } else {
                *reinterpret_cast<float2*>(C + (size_t)r0*N + col) =
                    make_float2(acc[mt][nt][0], acc[mt][nt][1]);
                *reinterpret_cast<float2*>(C + (size_t)(r0+8)*N + col) =
                    make_float2(acc[mt][nt][2], acc[mt][nt][3]);
            }
        }
    }
}

// ---- GQA-merged causal flash attention: 512 threads, 16 warps x 16 q-rows ----
// Same math per output element as the 256-thread version (bit-identical);
// re-partitioned so each warp owns one m16 tile -> 4 warps/SMSP latency cover.
__global__ __launch_bounds__(512) void flash_kernel(
    const float2* __restrict__ Qi, const float* __restrict__ Vhi,
    float* __restrict__ O)
{
    extern __shared__ float smf[];
    float2* Qs = reinterpret_cast<float2*>(smf);
    float2* Ks = reinterpret_cast<float2*>(smf + 256*QPAD*2);
    float*  Vs = smf + 256*QPAD*2 + 64*QPAD*2;

    int gcomb = blockIdx.x;
    int gkv = gcomb >> 1;
    int b   = gcomb & 1;
    int qb  = 31 - blockIdx.y;

    int tid = threadIdx.x;
    int wid = tid >> 5, lane = tid & 31;
    int g = lane >> 2, t = lane & 3;
    int hh = wid >> 2;               // head within kv group (0..3)
    int h  = gkv*4 + hh;
    int wr = (wid & 3) * 16;         // q-row base within head's 64 rows

    {
        size_t rowbase = (size_t)(b*SEQ + qb*64);
        #pragma unroll
        for (int it = 0; it < 16; it++) {
            int pidx = tid + it*512;
            int qrow = pidx >> 5;
            int c2 = pidx & 31;
            int head = gkv*4 + (qrow >> 6);
            size_t goff = (rowbase + (qrow & 63))*QKV_N + head*HD + c2*2;
            *reinterpret_cast<float4*>(&Qs[qrow*QPAD + c2*2]) =
                *reinterpret_cast<const float4*>(&Qi[goff]);
        }
    }

    float m_i[2] = {-INFINITY, -INFINITY};
    float l_i[2] = {0.f, 0.f};
    float o_acc[8][4];
    #pragma unroll
    for (int dt = 0; dt < 8; dt++)
        #pragma unroll
        for (int r = 0; r < 4; r++) o_acc[dt][r] = 0.f;

    for (int kb = 0; kb <= qb; kb++) {
        __syncthreads();
        {
            size_t krowbase = (size_t)(b*SEQ + kb*64);
            #pragma unroll
            for (int it = 0; it < 4; it++) {
                int pidx = tid + it*512;
                int kr = pidx >> 5, c2 = pidx & 31;
                size_t goff = (krowbase + kr)*QKV_N + DIMX + gkv*HD + c2*2;
                *reinterpret_cast<float4*>(&Ks[kr*QPAD + c2*2]) =
                    *reinterpret_cast<const float4*>(&Qi[goff]);
            }
            #pragma unroll
            for (int it = 0; it < 2; it++) {
                int fidx = tid + it*512;
                int vr = fidx >> 4, d4 = fidx & 15;
                size_t goff = (krowbase + vr)*KVDIM + gkv*HD + d4*4;
                *reinterpret_cast<float4*>(&Vs[vr*VPAD + d4*4]) =
                    *reinterpret_cast<const float4*>(Vhi + goff);
            }
        }
        __syncthreads();

        float s[8][4];
        #pragma unroll
        for (int nt = 0; nt < 8; nt++)
            #pragma unroll
            for (int r = 0; r < 4; r++) s[nt][r] = 0.f;

        #pragma unroll
        for (int ks = 0; ks < 8; ks++) {
            int kk = ks*8;
            uint32_t ah[4], al[4];
            {
                int row = hh*64 + wr + g;
                float2 q00 = Qs[row*QPAD + kk + t];
                float2 q01 = Qs[row*QPAD + kk + t + 4];
                float2 q10 = Qs[(row+8)*QPAD + kk + t];
                float2 q11 = Qs[(row+8)*QPAD + kk + t + 4];
                ah[0] = fu(q00.x); al[0] = fu(q00.y);
                ah[1] = fu(q10.x); al[1] = fu(q10.y);
                ah[2] = fu(q01.x); al[2] = fu(q01.y);
                ah[3] = fu(q11.x); al[3] = fu(q11.y);
            }
            #pragma unroll
            for (int nt = 0; nt < 8; nt++) {
                float2 k0 = Ks[(nt*8+g)*QPAD + kk + t];
                float2 k1 = Ks[(nt*8+g)*QPAD + kk + t + 4];
                uint32_t bh0 = fu(k0.x), bl0 = fu(k0.y);
                uint32_t bh1 = fu(k1.x), bl1 = fu(k1.y);
                MMA_TF32(s[nt], ah, bh0, bh1);
                MMA_TF32(s[nt], ah, bl0, bl1);
                MMA_TF32(s[nt], al, bh0, bh1);
            }
        }

        const float smul = 0.125f;
        if (kb == qb) {
            int qr = wr + g;
            #pragma unroll
            for (int nt = 0; nt < 8; nt++) {
                int c0 = nt*8 + t*2;
                s[nt][0] = (c0     <= qr)     ? s[nt][0]*smul : -INFINITY;
                s[nt][1] = (c0 + 1 <= qr)     ? s[nt][1]*smul : -INFINITY;
                s[nt][2] = (c0     <= qr + 8) ? s[nt][2]*smul : -INFINITY;
                s[nt][3] = (c0 + 1 <= qr + 8) ? s[nt][3]*smul : -INFINITY;
            }
        } else {
            #pragma unroll
            for (int nt = 0; nt < 8; nt++)
                #pragma unroll
                for (int r = 0; r < 4; r++) s[nt][r] *= smul;
        }

        #pragma unroll
        for (int rr = 0; rr < 2; rr++) {
            float mx = -INFINITY;
            #pragma unroll
            for (int nt = 0; nt < 8; nt++)
                mx = fmaxf(mx, fmaxf(s[nt][2*rr], s[nt][2*rr+1]));
            mx = fmaxf(mx, __shfl_xor_sync(0xffffffffu, mx, 1));
            mx = fmaxf(mx, __shfl_xor_sync(0xffffffffu, mx, 2));
            float m_new = fmaxf(m_i[rr], mx);
            float alpha = __expf(m_i[rr] - m_new);
            float rs = 0.f;
            #pragma unroll
            for (int nt = 0; nt < 8; nt++) {
                float p0 = __expf(s[nt][2*rr]   - m_new);
                float p1 = __expf(s[nt][2*rr+1] - m_new);
                s[nt][2*rr] = p0; s[nt][2*rr+1] = p1;
                rs += p0 + p1;
            }
            rs += __shfl_xor_sync(0xffffffffu, rs, 1);
            rs += __shfl_xor_sync(0xffffffffu, rs, 2);
            l_i[rr] = l_i[rr]*alpha + rs;
            m_i[rr] = m_new;
            #pragma unroll
            for (int dt = 0; dt < 8; dt++) {
                o_acc[dt][2*rr]   *= alpha;
                o_acc[dt][2*rr+1] *= alpha;
            }
        }

        #pragma unroll
        for (int ks = 0; ks < 8; ks++) {
            int kk = ks*8;
            uint32_t pa[4];
            int srcA = (lane & 28) | (t >> 1);
            int srcB = srcA + 2;
            {
                float x0 = __shfl_sync(0xffffffffu, s[ks][0], srcA);
                float x1 = __shfl_sync(0xffffffffu, s[ks][1], srcA);
                float y0 = __shfl_sync(0xffffffffu, s[ks][0], srcB);
                float y1 = __shfl_sync(0xffffffffu, s[ks][1], srcB);
                float x2 = __shfl_sync(0xffffffffu, s[ks][2], srcA);
                float x3 = __shfl_sync(0xffffffffu, s[ks][3], srcA);
                float y2 = __shfl_sync(0xffffffffu, s[ks][2], srcB);
                float y3 = __shfl_sync(0xffffffffu, s[ks][3], srcB);
                float a0 = (t & 1) ? x1 : x0;
                float a1 = (t & 1) ? x3 : x2;
                float a2 = (t & 1) ? y1 : y0;
                float a3 = (t & 1) ? y3 : y2;
                pa[0] = f2tf(a0); pa[1] = f2tf(a1);
                pa[2] = f2tf(a2); pa[3] = f2tf(a3);
            }
            #pragma unroll
            for (int dt = 0; dt < 8; dt++) {
                uint32_t v0 = fu(Vs[(kk+t)*VPAD + dt*8 + g]);
                uint32_t v1 = fu(Vs[(kk+t+4)*VPAD + dt*8 + g]);
                MMA_TF32(o_acc[dt], pa, v0, v1);
            }
        }
    }

    float inv0 = 1.f / l_i[0], inv1 = 1.f / l_i[1];
    float* Og = O + (size_t)(b*SEQ + qb*64 + wr + g)*DIMX + h*HD;
    #pragma unroll
    for (int dt = 0; dt < 8; dt++) {
        *reinterpret_cast<float2*>(Og + dt*8 + t*2) =
            make_float2(o_acc[dt][0]*inv0, o_acc[dt][1]*inv0);
        *reinterpret_cast<float2*>(Og + (size_t)8*DIMX + dt*8 + t*2) =
            make_float2(o_acc[dt][2]*inv1, o_acc[dt][3]*inv1);
    }
}

extern "C" void kernel_launch(void* const* d_in, const int* in_sizes, int n_in,
                              void* d_out, int out_size)
{
    const float* x  = (const float*)d_in[0];
    const float* wq = (const float*)d_in[1];
    const float* wk = (const float*)d_in[2];
    const float* wv = (const float*)d_in[3];
    const float* wo = (const float*)d_in[4];
    float* out = (float*)d_out;

    __nv_bfloat16 *w3, *to, *xs, *aos;
    float *qi, *vhi, *ao;
    cudaGetSymbolAddress((void**)&w3,  g_w);
    cudaGetSymbolAddress((void**)&to,  g_to);
    cudaGetSymbolAddress((void**)&xs,  g_xs);
    cudaGetSymbolAddress((void**)&aos, g_aos);
    cudaGetSymbolAddress((void**)&qi,  g_qi);
    cudaGetSymbolAddress((void**)&vhi, g_vhi);
    cudaGetSymbolAddress((void**)&ao,  g_ao);

    // 1) fused |w| mean + thresholds
    abs_all_kernel<<<dim3(256, 4), 256>>>((const float4*)wq, (const float4*)wk,
                                          (const float4*)wv, (const float4*)wo);
    finalize_kernel<<<4, 256>>>();

    // 2) fused ternarize + x 3-split
    tern_split_kernel<<<dim3(M_ROWS*DIMX/4/256, 5), 256>>>(
        (const float4*)wq, (const float4*)wk, (const float4*)wv, (const float4*)wo,
        (const float4*)x, (uint2*)w3, (uint2*)to, (uint2*)xs);

    // 3) QKV projection (R14 config: 3-stage, no occupancy cap)
    int gsm1 = 3 * 4*128*ALD2 * 4;
    cudaFuncSetAttribute(gemm_async<3,true>,
                         cudaFuncAttributeMaxDynamicSharedMemorySize, gsm1);
    gemm_async<3,true><<<dim3(QKV_N/128, M_ROWS/128), 256, gsm1>>>(
        xs, w3, qi, vhi, M_ROWS, QKV_N, DIMX);

    // 4) attention (GQA-merged, 512 threads / 16 warps)
    int fsm = (256*QPAD*2 + 64*QPAD*2 + 64*VPAD) * 4;
    cudaFuncSetAttribute(flash_kernel,
                         cudaFuncAttributeMaxDynamicSharedMemorySize, fsm);
    flash_kernel<<<dim3(16, 32), 512, fsm>>>((const float2*)qi, vhi, ao);

    // 5) pre-split ao into 2 bf16 planes
    split_bf2_kernel<<<(M_ROWS*DIMX/4)/256, 256>>>(
        (const float4*)ao, (uint2*)aos, M_ROWS*DIMX/4);

    // 6) output projection (R14 config)
    int gsm2 = 3 * 3*128*ALD2 * 4;
    cudaFuncSetAttribute(gemm_async<2,false>,
                         cudaFuncAttributeMaxDynamicSharedMemorySize, gsm2);
    gemm_async<2,false><<<dim3(DIMX/128, M_ROWS/128), 256, gsm2>>>(
        aos, to, out, nullptr, M_ROWS, DIMX, DIMX);
}